// round 9
// baseline (speedup 1.0000x reference)
#include <cuda_runtime.h>
#include <cuda_fp16.h>
#include <cuda_bf16.h>
#include <cstdint>

#define D_DIM 128
#define MAX_NODES 100000

// Per-node projections in fp16: row n = [P(16 half) | Q(16 half)] = 64 bytes.
// 100k * 64B = 6.4 MB -> trivially L2-resident. fp16 rounding adds ~3e-4
// norm-relative error (threshold 1e-3; GEMM itself is bf16x3 + fp32 accum).
__device__ __half g_PQh[(size_t)MAX_NODES * 32];
__device__ int g_idx64;

// Pack two floats into one bf16x2 register (low half = first arg).
__device__ __forceinline__ uint32_t packbf(float a, float b) {
    __nv_bfloat162 p = __floats2bfloat162_rn(a, b);
    return *reinterpret_cast<uint32_t*>(&p);
}

// m16n8k16 bf16 HMMA, fp32 accumulate (sm_80+; compiles on plain sm_100).
__device__ __forceinline__ void mma16816(float* c, uint32_t a0, uint32_t a1,
                                         uint32_t a2, uint32_t a3,
                                         uint32_t b0, uint32_t b1) {
    asm volatile(
        "mma.sync.aligned.m16n8k16.row.col.f32.bf16.bf16.f32 "
        "{%0,%1,%2,%3}, {%4,%5,%6,%7}, {%8,%9}, {%0,%1,%2,%3};"
        : "+f"(c[0]), "+f"(c[1]), "+f"(c[2]), "+f"(c[3])
        : "r"(a0), "r"(a1), "r"(a2), "r"(a3), "r"(b0), "r"(b1));
}

#define APAD 36   // kpairs/row for A k-tile (32+4): gid*36+tid4 mod 32 distinct
#define WPAD 68   // kpairs/row for W full-K (64+4): gid*68+tid4 mod 32 distinct

// smem layout (u32 units): sAhi[128*36]=0, sAlo=4608, sWhi[32*68]=9216, sWlo=11392
#define SM_ALO 4608
#define SM_WHI 9216
#define SM_WLO 11392
#define SMEM_BYTES (13568 * 4)

// ---------------------------------------------------------------------------
// Kernel 1: PQ = [128-node tile] x [32 cols] x K=128 GEMM via HMMA mma.sync,
// bf16x3 split (hi*Whi + hi*Wlo + lo*Whi, fp32 accum). 256 threads; warp w
// owns rows 16w..16w+15 x 32 cols. K tiled by 64; k-tile-1 A register-
// prefetched during k-tile-0 MMA. Epilogue stores fp16 (half2).
// Block 0 also detects int64 vs int32 edge indices.
// ---------------------------------------------------------------------------
__global__ __launch_bounds__(256) void precompute_kernel(const float* __restrict__ h,
                                                         const float* __restrict__ W,
                                                         const float* __restrict__ b,
                                                         const int* __restrict__ src_words,
                                                         int n_nodes) {
    extern __shared__ uint32_t smem[];
    uint32_t* sAhi = smem;
    uint32_t* sAlo = smem + SM_ALO;
    uint32_t* sWhi = smem + SM_WHI;
    uint32_t* sWlo = smem + SM_WLO;

    const int t = threadIdx.x;
    const int warp = t >> 5;
    const int lane = t & 31;
    const int gid = lane >> 2;   // fragment group 0..7
    const int tid4 = lane & 3;   // 0..3

    if (blockIdx.x == 0 && t < 32) {
        int ok = (src_words[t * 2 + 1] == 0);
        int all = __all_sync(0xffffffffu, ok);
        if (t == 0) g_idx64 = all;
    }

    const int n0 = blockIdx.x * 128;

    // ---- stage W for full K=128: out col j<16 -> W_s row j ; j>=16 -> W_d row j-16.
#pragma unroll
    for (int s = 0; s < 4; s++) {
        int idx = s * 256 + t;
        int col = idx >> 5;       // 0..31
        int f4 = idx & 31;        // float4 within 128 k-values
        float4 wv = *reinterpret_cast<const float4*>(
            W + (size_t)(col & 15) * 256 + ((col >> 4) << 7) + f4 * 4);
        float h0 = __bfloat162float(__float2bfloat16_rn(wv.x));
        float h1 = __bfloat162float(__float2bfloat16_rn(wv.y));
        float h2 = __bfloat162float(__float2bfloat16_rn(wv.z));
        float h3 = __bfloat162float(__float2bfloat16_rn(wv.w));
        uint2 hi = make_uint2(packbf(h0, h1), packbf(h2, h3));
        uint2 lo = make_uint2(packbf(wv.x - h0, wv.y - h1), packbf(wv.z - h2, wv.w - h3));
        *reinterpret_cast<uint2*>(&sWhi[col * WPAD + f4 * 2]) = hi;
        *reinterpret_cast<uint2*>(&sWlo[col * WPAD + f4 * 2]) = lo;
    }

    // ---- stage A k-tile 0 (k 0..63)
#pragma unroll
    for (int s = 0; s < 8; s++) {
        int idx = s * 256 + t;
        int row = idx >> 4;       // 0..127
        int f4 = idx & 15;        // float4 within 64 k-values
        int n = n0 + row;
        if (n > n_nodes - 1) n = n_nodes - 1;
        float4 v = *reinterpret_cast<const float4*>(h + (size_t)n * D_DIM + f4 * 4);
        float h0 = __bfloat162float(__float2bfloat16_rn(v.x));
        float h1 = __bfloat162float(__float2bfloat16_rn(v.y));
        float h2 = __bfloat162float(__float2bfloat16_rn(v.z));
        float h3 = __bfloat162float(__float2bfloat16_rn(v.w));
        *reinterpret_cast<uint2*>(&sAhi[row * APAD + f4 * 2]) =
            make_uint2(packbf(h0, h1), packbf(h2, h3));
        *reinterpret_cast<uint2*>(&sAlo[row * APAD + f4 * 2]) =
            make_uint2(packbf(v.x - h0, v.y - h1), packbf(v.z - h2, v.w - h3));
    }
    __syncthreads();

    // ---- prefetch k-tile 1 A (k 64..127) into registers (overlaps kt0 MMA)
    float4 pf[8];
#pragma unroll
    for (int s = 0; s < 8; s++) {
        int idx = s * 256 + t;
        int row = idx >> 4;
        int f4 = idx & 15;
        int n = n0 + row;
        if (n > n_nodes - 1) n = n_nodes - 1;
        pf[s] = *reinterpret_cast<const float4*>(h + (size_t)n * D_DIM + 64 + f4 * 4);
    }

    float acc[4][4];
#pragma unroll
    for (int nt = 0; nt < 4; nt++)
#pragma unroll
        for (int q = 0; q < 4; q++) acc[nt][q] = 0.f;

    // ---- MMA k-tile 0
#pragma unroll
    for (int ks = 0; ks < 4; ks++) {
        const int kb = ks * 8 + tid4;
        int r0 = (warp * 16 + gid) * APAD + kb;
        int r1 = r0 + 8 * APAD;
        uint32_t ah0 = sAhi[r0], ah1 = sAhi[r1], ah2 = sAhi[r0 + 4], ah3 = sAhi[r1 + 4];
        uint32_t al0 = sAlo[r0], al1 = sAlo[r1], al2 = sAlo[r0 + 4], al3 = sAlo[r1 + 4];
#pragma unroll
        for (int nt = 0; nt < 4; nt++) {
            int base = (nt * 8 + gid) * WPAD + kb;   // kt0: kpairs 0..31
            uint32_t b0 = sWhi[base], b1 = sWhi[base + 4];
            uint32_t l0 = sWlo[base], l1 = sWlo[base + 4];
            mma16816(acc[nt], ah0, ah1, ah2, ah3, b0, b1);
            mma16816(acc[nt], ah0, ah1, ah2, ah3, l0, l1);
            mma16816(acc[nt], al0, al1, al2, al3, b0, b1);
        }
    }
    __syncthreads();

    // ---- store prefetched k-tile 1 A
#pragma unroll
    for (int s = 0; s < 8; s++) {
        int idx = s * 256 + t;
        int row = idx >> 4;
        int f4 = idx & 15;
        float4 v = pf[s];
        float h0 = __bfloat162float(__float2bfloat16_rn(v.x));
        float h1 = __bfloat162float(__float2bfloat16_rn(v.y));
        float h2 = __bfloat162float(__float2bfloat16_rn(v.z));
        float h3 = __bfloat162float(__float2bfloat16_rn(v.w));
        *reinterpret_cast<uint2*>(&sAhi[row * APAD + f4 * 2]) =
            make_uint2(packbf(h0, h1), packbf(h2, h3));
        *reinterpret_cast<uint2*>(&sAlo[row * APAD + f4 * 2]) =
            make_uint2(packbf(v.x - h0, v.y - h1), packbf(v.z - h2, v.w - h3));
    }
    __syncthreads();

    // ---- MMA k-tile 1 (W kpairs 32..63)
#pragma unroll
    for (int ks = 0; ks < 4; ks++) {
        const int kb = ks * 8 + tid4;
        int r0 = (warp * 16 + gid) * APAD + kb;
        int r1 = r0 + 8 * APAD;
        uint32_t ah0 = sAhi[r0], ah1 = sAhi[r1], ah2 = sAhi[r0 + 4], ah3 = sAhi[r1 + 4];
        uint32_t al0 = sAlo[r0], al1 = sAlo[r1], al2 = sAlo[r0 + 4], al3 = sAlo[r1 + 4];
#pragma unroll
        for (int nt = 0; nt < 4; nt++) {
            int base = (nt * 8 + gid) * WPAD + 32 + kb;
            uint32_t b0 = sWhi[base], b1 = sWhi[base + 4];
            uint32_t l0 = sWlo[base], l1 = sWlo[base + 4];
            mma16816(acc[nt], ah0, ah1, ah2, ah3, b0, b1);
            mma16816(acc[nt], ah0, ah1, ah2, ah3, l0, l1);
            mma16816(acc[nt], al0, al1, al2, al3, b0, b1);
        }
    }

    // ---- epilogue: c0,c1 -> row gid, c2,c3 -> row gid+8; bias on cols<16;
    //      store as half2.
#pragma unroll
    for (int nt = 0; nt < 4; nt++) {
        int col = nt * 8 + 2 * tid4;
        float2 bias = make_float2(0.f, 0.f);
        if (nt < 2) bias = *reinterpret_cast<const float2*>(b + col);
        int row0 = n0 + warp * 16 + gid;
        if (row0 < n_nodes)
            *reinterpret_cast<__half2*>(g_PQh + (size_t)row0 * 32 + col) =
                __floats2half2_rn(acc[nt][0] + bias.x, acc[nt][1] + bias.y);
        if (row0 + 8 < n_nodes)
            *reinterpret_cast<__half2*>(g_PQh + (size_t)(row0 + 8) * 32 + col) =
                __floats2half2_rn(acc[nt][2] + bias.x, acc[nt][3] + bias.y);
    }
}

// ---------------------------------------------------------------------------
// Kernel 2: out[e][c] = float(Ph[src[e]][c]) + float(Qh[dst[e]][c]).
// fp16 PQ rows are 64B: P = 1 sector, Q = 1 sector -> half the L1 fill work
// and 4x less L2 gather traffic vs fp32. 2 lanes per edge (16B of halves
// each); 64 edges/warp; all 8 gather loads batched before processing.
// ---------------------------------------------------------------------------
__global__ __launch_bounds__(256) void gather_kernel(const void* __restrict__ src_raw,
                                                     const void* __restrict__ dst_raw,
                                                     float* __restrict__ out,
                                                     int n_edges) {
    const int lane = threadIdx.x & 31;
    const long long wid = (long long)blockIdx.x * (blockDim.x >> 5) + (threadIdx.x >> 5);
    const long long e0 = wid * 64;
    if (e0 >= n_edges) return;

    long long ea = e0 + lane, eb = e0 + 32 + lane;
    if (ea > n_edges - 1) ea = n_edges - 1;
    if (eb > n_edges - 1) eb = n_edges - 1;

    int s0, s1, d0, d1;
    if (g_idx64) {
        s0 = (int)__ldcs(reinterpret_cast<const long long*>(src_raw) + ea);
        s1 = (int)__ldcs(reinterpret_cast<const long long*>(src_raw) + eb);
        d0 = (int)__ldcs(reinterpret_cast<const long long*>(dst_raw) + ea);
        d1 = (int)__ldcs(reinterpret_cast<const long long*>(dst_raw) + eb);
    } else {
        s0 = __ldcs(reinterpret_cast<const int*>(src_raw) + ea);
        s1 = __ldcs(reinterpret_cast<const int*>(src_raw) + eb);
        d0 = __ldcs(reinterpret_cast<const int*>(dst_raw) + ea);
        d1 = __ldcs(reinterpret_cast<const int*>(dst_raw) + eb);
    }

    const int esub = lane >> 1;   // edge-in-pass 0..15
    const int comp = lane & 1;    // which 8-half chunk of the 16-half row

    // Phase 1: all 8 gather loads (clamped idx -> always-safe addresses).
    uint4 pv[4], qv[4];
#pragma unroll
    for (int p = 0; p < 4; p++) {
        int srcl = ((p & 1) << 4) + esub;       // (p*16+esub) & 31
        int se = __shfl_sync(0xffffffffu, (p < 2) ? s0 : s1, srcl);
        int de = __shfl_sync(0xffffffffu, (p < 2) ? d0 : d1, srcl);
        pv[p] = __ldcg(reinterpret_cast<const uint4*>(
            g_PQh + (size_t)se * 32 + comp * 8));
        qv[p] = __ldcg(reinterpret_cast<const uint4*>(
            g_PQh + (size_t)de * 32 + 16 + comp * 8));
    }

    // Phase 2: convert, add, guarded store (32B per lane = 2 float4).
#pragma unroll
    for (int p = 0; p < 4; p++) {
        long long eg = e0 + p * 16 + esub;
        if (eg < n_edges) {
            const __half2* ph = reinterpret_cast<const __half2*>(&pv[p]);
            const __half2* qh = reinterpret_cast<const __half2*>(&qv[p]);
            float r[8];
#pragma unroll
            for (int i = 0; i < 4; i++) {
                float2 a = __half22float2(ph[i]);
                float2 c = __half22float2(qh[i]);
                r[2 * i] = a.x + c.x;
                r[2 * i + 1] = a.y + c.y;
            }
            float4* o = reinterpret_cast<float4*>(out + eg * 16 + comp * 8);
            __stcs(o, make_float4(r[0], r[1], r[2], r[3]));
            __stcs(o + 1, make_float4(r[4], r[5], r[6], r[7]));
        }
    }
}

// ---------------------------------------------------------------------------
// Inputs (metadata order): h [N*128 f32], src [E idx], dst [E idx],
//                          W [16*256 f32], b [16 f32]. Output: [E*16 f32].
// ---------------------------------------------------------------------------
extern "C" void kernel_launch(void* const* d_in, const int* in_sizes, int n_in,
                              void* d_out, int out_size) {
    const float* h = (const float*)d_in[0];
    const void* src = d_in[1];
    const void* dst = d_in[2];
    const float* W = (const float*)d_in[3];
    const float* b = (const float*)d_in[4];

    int n_nodes = in_sizes[0] / D_DIM;
    int n_edges = in_sizes[1];

    cudaFuncSetAttribute(precompute_kernel,
                         cudaFuncAttributeMaxDynamicSharedMemorySize, SMEM_BYTES);

    int blocks1 = (n_nodes + 127) / 128;
    precompute_kernel<<<blocks1, 256, SMEM_BYTES>>>(h, W, b, (const int*)src, n_nodes);

    long long warps = ((long long)n_edges + 63) / 64;
    int blocks2 = (int)((warps + 7) / 8);
    gather_kernel<<<blocks2, 256>>>(src, dst, (float*)d_out, n_edges);
}

// round 10
// speedup vs baseline: 1.1979x; 1.1979x over previous
#include <cuda_runtime.h>
#include <cuda_fp16.h>
#include <cuda_bf16.h>
#include <cstdint>

#define D_DIM 128
#define MAX_NODES 100000

// Per-node projections in fp16: row n = [P(16 half) | Q(16 half)] = 64 bytes.
// 100k * 64B = 6.4 MB -> trivially L2-resident. fp16 rounding adds ~2e-4
// norm-relative error (threshold 1e-3; GEMM itself is bf16x3 + fp32 accum).
__device__ __half g_PQh[(size_t)MAX_NODES * 32];
__device__ int g_idx64;

// Pack two floats into one bf16x2 register (low half = first arg).
__device__ __forceinline__ uint32_t packbf(float a, float b) {
    __nv_bfloat162 p = __floats2bfloat162_rn(a, b);
    return *reinterpret_cast<uint32_t*>(&p);
}

// m16n8k16 bf16 HMMA, fp32 accumulate (sm_80+; compiles on plain sm_100).
__device__ __forceinline__ void mma16816(float* c, uint32_t a0, uint32_t a1,
                                         uint32_t a2, uint32_t a3,
                                         uint32_t b0, uint32_t b1) {
    asm volatile(
        "mma.sync.aligned.m16n8k16.row.col.f32.bf16.bf16.f32 "
        "{%0,%1,%2,%3}, {%4,%5,%6,%7}, {%8,%9}, {%0,%1,%2,%3};"
        : "+f"(c[0]), "+f"(c[1]), "+f"(c[2]), "+f"(c[3])
        : "r"(a0), "r"(a1), "r"(a2), "r"(a3), "r"(b0), "r"(b1));
}

#define APAD 36   // kpairs/row for A k-tile (32+4): gid*36+tid4 mod 32 distinct
#define WPAD 68   // kpairs/row for W full-K (64+4): gid*68+tid4 mod 32 distinct

// smem layout (u32 units): sAhi[128*36]=0, sAlo=4608, sWhi[32*68]=9216, sWlo=11392
#define SM_ALO 4608
#define SM_WHI 9216
#define SM_WLO 11392
#define SMEM_BYTES (13568 * 4)

// ---------------------------------------------------------------------------
// Kernel 1: PQ = [128-node tile] x [32 cols] x K=128 GEMM via HMMA mma.sync,
// bf16x3 split (hi*Whi + hi*Wlo + lo*Whi, fp32 accum). 256 threads; warp w
// owns rows 16w..16w+15 x 32 cols. K tiled by 64; k-tile-1 A register-
// prefetched during k-tile-0 MMA. Epilogue stores fp16 (half2).
// Block 0 also detects int64 vs int32 edge indices.
// ---------------------------------------------------------------------------
__global__ __launch_bounds__(256) void precompute_kernel(const float* __restrict__ h,
                                                         const float* __restrict__ W,
                                                         const float* __restrict__ b,
                                                         const int* __restrict__ src_words,
                                                         int n_nodes) {
    extern __shared__ uint32_t smem[];
    uint32_t* sAhi = smem;
    uint32_t* sAlo = smem + SM_ALO;
    uint32_t* sWhi = smem + SM_WHI;
    uint32_t* sWlo = smem + SM_WLO;

    const int t = threadIdx.x;
    const int warp = t >> 5;
    const int lane = t & 31;
    const int gid = lane >> 2;   // fragment group 0..7
    const int tid4 = lane & 3;   // 0..3

    if (blockIdx.x == 0 && t < 32) {
        int ok = (src_words[t * 2 + 1] == 0);
        int all = __all_sync(0xffffffffu, ok);
        if (t == 0) g_idx64 = all;
    }

    const int n0 = blockIdx.x * 128;

    // ---- stage W for full K=128: out col j<16 -> W_s row j ; j>=16 -> W_d row j-16.
#pragma unroll
    for (int s = 0; s < 4; s++) {
        int idx = s * 256 + t;
        int col = idx >> 5;       // 0..31
        int f4 = idx & 31;        // float4 within 128 k-values
        float4 wv = *reinterpret_cast<const float4*>(
            W + (size_t)(col & 15) * 256 + ((col >> 4) << 7) + f4 * 4);
        float h0 = __bfloat162float(__float2bfloat16_rn(wv.x));
        float h1 = __bfloat162float(__float2bfloat16_rn(wv.y));
        float h2 = __bfloat162float(__float2bfloat16_rn(wv.z));
        float h3 = __bfloat162float(__float2bfloat16_rn(wv.w));
        uint2 hi = make_uint2(packbf(h0, h1), packbf(h2, h3));
        uint2 lo = make_uint2(packbf(wv.x - h0, wv.y - h1), packbf(wv.z - h2, wv.w - h3));
        *reinterpret_cast<uint2*>(&sWhi[col * WPAD + f4 * 2]) = hi;
        *reinterpret_cast<uint2*>(&sWlo[col * WPAD + f4 * 2]) = lo;
    }

    // ---- stage A k-tile 0 (k 0..63)
#pragma unroll
    for (int s = 0; s < 8; s++) {
        int idx = s * 256 + t;
        int row = idx >> 4;       // 0..127
        int f4 = idx & 15;        // float4 within 64 k-values
        int n = n0 + row;
        if (n > n_nodes - 1) n = n_nodes - 1;
        float4 v = *reinterpret_cast<const float4*>(h + (size_t)n * D_DIM + f4 * 4);
        float h0 = __bfloat162float(__float2bfloat16_rn(v.x));
        float h1 = __bfloat162float(__float2bfloat16_rn(v.y));
        float h2 = __bfloat162float(__float2bfloat16_rn(v.z));
        float h3 = __bfloat162float(__float2bfloat16_rn(v.w));
        *reinterpret_cast<uint2*>(&sAhi[row * APAD + f4 * 2]) =
            make_uint2(packbf(h0, h1), packbf(h2, h3));
        *reinterpret_cast<uint2*>(&sAlo[row * APAD + f4 * 2]) =
            make_uint2(packbf(v.x - h0, v.y - h1), packbf(v.z - h2, v.w - h3));
    }
    __syncthreads();

    // ---- prefetch k-tile 1 A (k 64..127) into registers (overlaps kt0 MMA)
    float4 pf[8];
#pragma unroll
    for (int s = 0; s < 8; s++) {
        int idx = s * 256 + t;
        int row = idx >> 4;
        int f4 = idx & 15;
        int n = n0 + row;
        if (n > n_nodes - 1) n = n_nodes - 1;
        pf[s] = *reinterpret_cast<const float4*>(h + (size_t)n * D_DIM + 64 + f4 * 4);
    }

    float acc[4][4];
#pragma unroll
    for (int nt = 0; nt < 4; nt++)
#pragma unroll
        for (int q = 0; q < 4; q++) acc[nt][q] = 0.f;

    // ---- MMA k-tile 0
#pragma unroll
    for (int ks = 0; ks < 4; ks++) {
        const int kb = ks * 8 + tid4;
        int r0 = (warp * 16 + gid) * APAD + kb;
        int r1 = r0 + 8 * APAD;
        uint32_t ah0 = sAhi[r0], ah1 = sAhi[r1], ah2 = sAhi[r0 + 4], ah3 = sAhi[r1 + 4];
        uint32_t al0 = sAlo[r0], al1 = sAlo[r1], al2 = sAlo[r0 + 4], al3 = sAlo[r1 + 4];
#pragma unroll
        for (int nt = 0; nt < 4; nt++) {
            int base = (nt * 8 + gid) * WPAD + kb;   // kt0: kpairs 0..31
            uint32_t b0 = sWhi[base], b1 = sWhi[base + 4];
            uint32_t l0 = sWlo[base], l1 = sWlo[base + 4];
            mma16816(acc[nt], ah0, ah1, ah2, ah3, b0, b1);
            mma16816(acc[nt], ah0, ah1, ah2, ah3, l0, l1);
            mma16816(acc[nt], al0, al1, al2, al3, b0, b1);
        }
    }
    __syncthreads();

    // ---- store prefetched k-tile 1 A
#pragma unroll
    for (int s = 0; s < 8; s++) {
        int idx = s * 256 + t;
        int row = idx >> 4;
        int f4 = idx & 15;
        float4 v = pf[s];
        float h0 = __bfloat162float(__float2bfloat16_rn(v.x));
        float h1 = __bfloat162float(__float2bfloat16_rn(v.y));
        float h2 = __bfloat162float(__float2bfloat16_rn(v.z));
        float h3 = __bfloat162float(__float2bfloat16_rn(v.w));
        *reinterpret_cast<uint2*>(&sAhi[row * APAD + f4 * 2]) =
            make_uint2(packbf(h0, h1), packbf(h2, h3));
        *reinterpret_cast<uint2*>(&sAlo[row * APAD + f4 * 2]) =
            make_uint2(packbf(v.x - h0, v.y - h1), packbf(v.z - h2, v.w - h3));
    }
    __syncthreads();

    // ---- MMA k-tile 1 (W kpairs 32..63)
#pragma unroll
    for (int ks = 0; ks < 4; ks++) {
        const int kb = ks * 8 + tid4;
        int r0 = (warp * 16 + gid) * APAD + kb;
        int r1 = r0 + 8 * APAD;
        uint32_t ah0 = sAhi[r0], ah1 = sAhi[r1], ah2 = sAhi[r0 + 4], ah3 = sAhi[r1 + 4];
        uint32_t al0 = sAlo[r0], al1 = sAlo[r1], al2 = sAlo[r0 + 4], al3 = sAlo[r1 + 4];
#pragma unroll
        for (int nt = 0; nt < 4; nt++) {
            int base = (nt * 8 + gid) * WPAD + 32 + kb;
            uint32_t b0 = sWhi[base], b1 = sWhi[base + 4];
            uint32_t l0 = sWlo[base], l1 = sWlo[base + 4];
            mma16816(acc[nt], ah0, ah1, ah2, ah3, b0, b1);
            mma16816(acc[nt], ah0, ah1, ah2, ah3, l0, l1);
            mma16816(acc[nt], al0, al1, al2, al3, b0, b1);
        }
    }

    // ---- epilogue: c0,c1 -> row gid, c2,c3 -> row gid+8; bias on cols<16;
    //      store as half2.
#pragma unroll
    for (int nt = 0; nt < 4; nt++) {
        int col = nt * 8 + 2 * tid4;
        float2 bias = make_float2(0.f, 0.f);
        if (nt < 2) bias = *reinterpret_cast<const float2*>(b + col);
        int row0 = n0 + warp * 16 + gid;
        if (row0 < n_nodes)
            *reinterpret_cast<__half2*>(g_PQh + (size_t)row0 * 32 + col) =
                __floats2half2_rn(acc[nt][0] + bias.x, acc[nt][1] + bias.y);
        if (row0 + 8 < n_nodes)
            *reinterpret_cast<__half2*>(g_PQh + (size_t)(row0 + 8) * 32 + col) =
                __floats2half2_rn(acc[nt][2] + bias.x, acc[nt][3] + bias.y);
    }
}

// ---------------------------------------------------------------------------
// Kernel 2: out[e][c] = float(Ph[src[e]][c]) + float(Qh[dst[e]][c]).
// R8's proven structure (4 lanes/edge, contiguous float4 stores) with fp16
// PQ: each lane gathers 8B of P (uint2) + 8B of Q. P row = 32B = 1 sector,
// fully covered by the 4 lanes -> no partial sectors on loads OR stores;
// gather sector traffic halved vs fp32. 64 edges/warp, loads batched first.
// ---------------------------------------------------------------------------
__global__ __launch_bounds__(256) void gather_kernel(const void* __restrict__ src_raw,
                                                     const void* __restrict__ dst_raw,
                                                     float* __restrict__ out,
                                                     int n_edges) {
    const int lane = threadIdx.x & 31;
    const long long wid = (long long)blockIdx.x * (blockDim.x >> 5) + (threadIdx.x >> 5);
    const long long e0 = wid * 64;
    if (e0 >= n_edges) return;

    long long ea = e0 + lane, eb = e0 + 32 + lane;
    if (ea > n_edges - 1) ea = n_edges - 1;
    if (eb > n_edges - 1) eb = n_edges - 1;

    int s0, s1, d0, d1;
    if (g_idx64) {
        s0 = (int)__ldcs(reinterpret_cast<const long long*>(src_raw) + ea);
        s1 = (int)__ldcs(reinterpret_cast<const long long*>(src_raw) + eb);
        d0 = (int)__ldcs(reinterpret_cast<const long long*>(dst_raw) + ea);
        d1 = (int)__ldcs(reinterpret_cast<const long long*>(dst_raw) + eb);
    } else {
        s0 = __ldcs(reinterpret_cast<const int*>(src_raw) + ea);
        s1 = __ldcs(reinterpret_cast<const int*>(src_raw) + eb);
        d0 = __ldcs(reinterpret_cast<const int*>(dst_raw) + ea);
        d1 = __ldcs(reinterpret_cast<const int*>(dst_raw) + eb);
    }

    const int sub = lane >> 2;    // edge-in-group 0..7
    const int comp = lane & 3;    // 4-half (8B) chunk within 16-half row

#pragma unroll
    for (int half = 0; half < 2; half++) {
        const int sv = half ? s1 : s0;
        const int dv = half ? d1 : d0;
        const long long ebase = e0 + half * 32 + sub;

        // Phase 1: issue all 8 gather loads (clamped idx -> always safe).
        uint2 pv[4], qv[4];
#pragma unroll
        for (int g = 0; g < 4; g++) {
            int se = __shfl_sync(0xffffffffu, sv, g * 8 + sub);
            int de = __shfl_sync(0xffffffffu, dv, g * 8 + sub);
            pv[g] = __ldcg(reinterpret_cast<const uint2*>(
                g_PQh + (size_t)se * 32) + comp);
            qv[g] = __ldcg(reinterpret_cast<const uint2*>(
                g_PQh + (size_t)de * 32 + 16) + comp);
        }

        // Phase 2: convert, add, guarded contiguous float4 store.
#pragma unroll
        for (int g = 0; g < 4; g++) {
            long long eg = ebase + g * 8;
            if (eg < n_edges) {
                __half2 p0 = *reinterpret_cast<const __half2*>(&pv[g].x);
                __half2 p1 = *reinterpret_cast<const __half2*>(&pv[g].y);
                __half2 q0 = *reinterpret_cast<const __half2*>(&qv[g].x);
                __half2 q1 = *reinterpret_cast<const __half2*>(&qv[g].y);
                float2 a0 = __half22float2(p0), c0 = __half22float2(q0);
                float2 a1 = __half22float2(p1), c1 = __half22float2(q1);
                float4 r = make_float4(a0.x + c0.x, a0.y + c0.y,
                                       a1.x + c1.x, a1.y + c1.y);
                __stcs(reinterpret_cast<float4*>(out) + eg * 4 + comp, r);
            }
        }
    }
}

// ---------------------------------------------------------------------------
// Inputs (metadata order): h [N*128 f32], src [E idx], dst [E idx],
//                          W [16*256 f32], b [16 f32]. Output: [E*16 f32].
// ---------------------------------------------------------------------------
extern "C" void kernel_launch(void* const* d_in, const int* in_sizes, int n_in,
                              void* d_out, int out_size) {
    const float* h = (const float*)d_in[0];
    const void* src = d_in[1];
    const void* dst = d_in[2];
    const float* W = (const float*)d_in[3];
    const float* b = (const float*)d_in[4];

    int n_nodes = in_sizes[0] / D_DIM;
    int n_edges = in_sizes[1];

    cudaFuncSetAttribute(precompute_kernel,
                         cudaFuncAttributeMaxDynamicSharedMemorySize, SMEM_BYTES);

    int blocks1 = (n_nodes + 127) / 128;
    precompute_kernel<<<blocks1, 256, SMEM_BYTES>>>(h, W, b, (const int*)src, n_nodes);

    long long warps = ((long long)n_edges + 63) / 64;
    int blocks2 = (int)((warps + 7) / 8);
    gather_kernel<<<blocks2, 256>>>(src, dst, (float*)d_out, n_edges);
}

// round 11
// speedup vs baseline: 1.2691x; 1.0595x over previous
#include <cuda_runtime.h>
#include <cuda_fp16.h>
#include <cstdint>

#define D_DIM 128
#define MAX_NODES 100000

// Per-node projections in fp16: row n = [P(16 half) | Q(16 half)] = 64 bytes.
// 6.4 MB -> L2-resident. Error budget: fp16 GEMM ~2.5e-4 + fp16 PQ ~2.1e-4
// => ~3.3e-4 combined, 3x under the 1e-3 threshold.
__device__ __half g_PQh[(size_t)MAX_NODES * 32];
__device__ int g_idx64;

// m16n8k16 fp16 HMMA, fp32 accumulate (sm_80+; compiles on plain sm_100).
__device__ __forceinline__ void mma16816(float* c, uint32_t a0, uint32_t a1,
                                         uint32_t a2, uint32_t a3,
                                         uint32_t b0, uint32_t b1) {
    asm volatile(
        "mma.sync.aligned.m16n8k16.row.col.f32.f16.f16.f32 "
        "{%0,%1,%2,%3}, {%4,%5,%6,%7}, {%8,%9}, {%0,%1,%2,%3};"
        : "+f"(c[0]), "+f"(c[1]), "+f"(c[2]), "+f"(c[3])
        : "r"(a0), "r"(a1), "r"(a2), "r"(a3), "r"(b0), "r"(b1));
}

__device__ __forceinline__ uint32_t packh2(float a, float b) {
    __half2 p = __floats2half2_rn(a, b);   // .x = a (low 16)
    return *reinterpret_cast<uint32_t*>(&p);
}

#define PAD 68    // u32 row stride (64 + 4): (row*68 + 4*gid + tid4) conflict-free
// smem: sA [128][68] u32 then sW [32][68] u32 -> 160*68*4 = 43,520 B
#define SM_W (128 * PAD)
#define SMEM_BYTES (160 * PAD * 4)

// ---------------------------------------------------------------------------
// Kernel 1: PQ = [128-node tile] x [32 cols] x K=128 GEMM, single-pass fp16
// HMMA with fp32 accumulation. 256 threads; warp w owns rows 16w..16w+15 x
// all 32 cols. Full K staged once (no k-tiling), one __syncthreads.
// Block 0 also detects int64 vs int32 edge indices (ids < 100k => int64 odd
// words all zero; int32 random ids false-positive ~1e-160).
// ---------------------------------------------------------------------------
__global__ __launch_bounds__(256) void precompute_kernel(const float* __restrict__ h,
                                                         const float* __restrict__ W,
                                                         const float* __restrict__ b,
                                                         const int* __restrict__ src_words,
                                                         int n_nodes) {
    extern __shared__ uint32_t smem[];
    uint32_t* sA = smem;          // [row][kpair] fp16x2
    uint32_t* sW = smem + SM_W;   // [out col][kpair] fp16x2

    const int t = threadIdx.x;
    const int warp = t >> 5;
    const int lane = t & 31;
    const int gid = lane >> 2;    // fragment group 0..7
    const int tid4 = lane & 3;    // 0..3

    if (blockIdx.x == 0 && t < 32) {
        int ok = (src_words[t * 2 + 1] == 0);
        int all = __all_sync(0xffffffffu, ok);
        if (t == 0) g_idx64 = all;
    }

    const int n0 = blockIdx.x * 128;

    // ---- stage W (full K): out col j<16 -> W_s row j ; j>=16 -> W_d row j-16.
    // 32 cols x 32 float4-chunks = 1024 chunks, 4 per thread.
#pragma unroll
    for (int s = 0; s < 4; s++) {
        int idx = s * 256 + t;
        int col = idx >> 5;        // 0..31
        int f4 = idx & 31;         // float4 within 128 k-values
        float4 wv = *reinterpret_cast<const float4*>(
            W + (size_t)(col & 15) * 256 + ((col >> 4) << 7) + f4 * 4);
        *reinterpret_cast<uint2*>(&sW[col * PAD + f4 * 2]) =
            make_uint2(packh2(wv.x, wv.y), packh2(wv.z, wv.w));
    }

    // ---- stage A (full K): 128 rows x 32 float4-chunks = 4096 chunks, 16/thread.
    // Each warp covers one full row (512B) per step -> coalesced.
#pragma unroll
    for (int s = 0; s < 16; s++) {
        int idx = s * 256 + t;
        int row = idx >> 5;        // 0..127
        int f4 = idx & 31;
        int n = n0 + row;
        if (n > n_nodes - 1) n = n_nodes - 1;
        float4 v = *reinterpret_cast<const float4*>(h + (size_t)n * D_DIM + f4 * 4);
        *reinterpret_cast<uint2*>(&sA[row * PAD + f4 * 2]) =
            make_uint2(packh2(v.x, v.y), packh2(v.z, v.w));
    }
    __syncthreads();

    // ---- MMA: 8 k16 steps x 4 n8 tiles = 32 HMMA per warp, single pass.
    float acc[4][4];
#pragma unroll
    for (int nt = 0; nt < 4; nt++)
#pragma unroll
        for (int q = 0; q < 4; q++) acc[nt][q] = 0.f;

#pragma unroll
    for (int ks = 0; ks < 8; ks++) {
        const int kb = ks * 8 + tid4;
        int r0 = (warp * 16 + gid) * PAD + kb;
        int r1 = r0 + 8 * PAD;
        uint32_t a0 = sA[r0], a1 = sA[r1], a2 = sA[r0 + 4], a3 = sA[r1 + 4];
#pragma unroll
        for (int nt = 0; nt < 4; nt++) {
            int base = (nt * 8 + gid) * PAD + kb;
            mma16816(acc[nt], a0, a1, a2, a3, sW[base], sW[base + 4]);
        }
    }

    // ---- epilogue: c0,c1 -> row gid, c2,c3 -> row gid+8; bias on cols<16;
    //      store as half2.
#pragma unroll
    for (int nt = 0; nt < 4; nt++) {
        int col = nt * 8 + 2 * tid4;
        float2 bias = make_float2(0.f, 0.f);
        if (nt < 2) bias = *reinterpret_cast<const float2*>(b + col);
        int row0 = n0 + warp * 16 + gid;
        if (row0 < n_nodes)
            *reinterpret_cast<__half2*>(g_PQh + (size_t)row0 * 32 + col) =
                __floats2half2_rn(acc[nt][0] + bias.x, acc[nt][1] + bias.y);
        if (row0 + 8 < n_nodes)
            *reinterpret_cast<__half2*>(g_PQh + (size_t)(row0 + 8) * 32 + col) =
                __floats2half2_rn(acc[nt][2] + bias.x, acc[nt][3] + bias.y);
    }
}

// ---------------------------------------------------------------------------
// Kernel 2 (unchanged from R10, 31.1us): out[e][c] = Ph[src[e]][c] + Qh[dst[e]][c].
// 4 lanes/edge, 8B gathers (P row = 1 sector), contiguous float4 stores,
// 64 edges/warp, all 8 gather loads batched before processing.
// ---------------------------------------------------------------------------
__global__ __launch_bounds__(256) void gather_kernel(const void* __restrict__ src_raw,
                                                     const void* __restrict__ dst_raw,
                                                     float* __restrict__ out,
                                                     int n_edges) {
    const int lane = threadIdx.x & 31;
    const long long wid = (long long)blockIdx.x * (blockDim.x >> 5) + (threadIdx.x >> 5);
    const long long e0 = wid * 64;
    if (e0 >= n_edges) return;

    long long ea = e0 + lane, eb = e0 + 32 + lane;
    if (ea > n_edges - 1) ea = n_edges - 1;
    if (eb > n_edges - 1) eb = n_edges - 1;

    int s0, s1, d0, d1;
    if (g_idx64) {
        s0 = (int)__ldcs(reinterpret_cast<const long long*>(src_raw) + ea);
        s1 = (int)__ldcs(reinterpret_cast<const long long*>(src_raw) + eb);
        d0 = (int)__ldcs(reinterpret_cast<const long long*>(dst_raw) + ea);
        d1 = (int)__ldcs(reinterpret_cast<const long long*>(dst_raw) + eb);
    } else {
        s0 = __ldcs(reinterpret_cast<const int*>(src_raw) + ea);
        s1 = __ldcs(reinterpret_cast<const int*>(src_raw) + eb);
        d0 = __ldcs(reinterpret_cast<const int*>(dst_raw) + ea);
        d1 = __ldcs(reinterpret_cast<const int*>(dst_raw) + eb);
    }

    const int sub = lane >> 2;    // edge-in-group 0..7
    const int comp = lane & 3;    // 4-half (8B) chunk within 16-half row

#pragma unroll
    for (int half = 0; half < 2; half++) {
        const int sv = half ? s1 : s0;
        const int dv = half ? d1 : d0;
        const long long ebase = e0 + half * 32 + sub;

        // Phase 1: issue all 8 gather loads (clamped idx -> always safe).
        uint2 pv[4], qv[4];
#pragma unroll
        for (int g = 0; g < 4; g++) {
            int se = __shfl_sync(0xffffffffu, sv, g * 8 + sub);
            int de = __shfl_sync(0xffffffffu, dv, g * 8 + sub);
            pv[g] = __ldcg(reinterpret_cast<const uint2*>(
                g_PQh + (size_t)se * 32) + comp);
            qv[g] = __ldcg(reinterpret_cast<const uint2*>(
                g_PQh + (size_t)de * 32 + 16) + comp);
        }

        // Phase 2: convert, add, guarded contiguous float4 store.
#pragma unroll
        for (int g = 0; g < 4; g++) {
            long long eg = ebase + g * 8;
            if (eg < n_edges) {
                __half2 p0 = *reinterpret_cast<const __half2*>(&pv[g].x);
                __half2 p1 = *reinterpret_cast<const __half2*>(&pv[g].y);
                __half2 q0 = *reinterpret_cast<const __half2*>(&qv[g].x);
                __half2 q1 = *reinterpret_cast<const __half2*>(&qv[g].y);
                float2 a0 = __half22float2(p0), c0 = __half22float2(q0);
                float2 a1 = __half22float2(p1), c1 = __half22float2(q1);
                float4 r = make_float4(a0.x + c0.x, a0.y + c0.y,
                                       a1.x + c1.x, a1.y + c1.y);
                __stcs(reinterpret_cast<float4*>(out) + eg * 4 + comp, r);
            }
        }
    }
}

// ---------------------------------------------------------------------------
// Inputs (metadata order): h [N*128 f32], src [E idx], dst [E idx],
//                          W [16*256 f32], b [16 f32]. Output: [E*16 f32].
// ---------------------------------------------------------------------------
extern "C" void kernel_launch(void* const* d_in, const int* in_sizes, int n_in,
                              void* d_out, int out_size) {
    const float* h = (const float*)d_in[0];
    const void* src = d_in[1];
    const void* dst = d_in[2];
    const float* W = (const float*)d_in[3];
    const float* b = (const float*)d_in[4];

    int n_nodes = in_sizes[0] / D_DIM;
    int n_edges = in_sizes[1];

    cudaFuncSetAttribute(precompute_kernel,
                         cudaFuncAttributeMaxDynamicSharedMemorySize, SMEM_BYTES);

    int blocks1 = (n_nodes + 127) / 128;
    precompute_kernel<<<blocks1, 256, SMEM_BYTES>>>(h, W, b, (const int*)src, n_nodes);

    long long warps = ((long long)n_edges + 63) / 64;
    int blocks2 = (int)((warps + 7) / 8);
    gather_kernel<<<blocks2, 256>>>(src, dst, (float*)d_out, n_edges);
}